// round 10
// baseline (speedup 1.0000x reference)
#include <cuda_runtime.h>
#include <cuda_fp16.h>
#include <cstdint>

#define BATCH   16384
#define HID     512
#define NLAYERS 8
#define NOUT    16
#define WSCALE  4.4194173824159215e-04f  /* 0.01 / sqrt(512) */
#define BSCALE  0.01f
#define SLOPE   0.2f
#define GAIN    1.41421356237f
#define EPSV    1e-8f

/* Fixed quantization scales (power-of-2).
   weights:  wh8 = wh * 2^15      (|w_eff| <= 2.4e-3, range 127*2^-15 = 3.9e-3)
             wl8 = (weff-wh)*2^26 (|wl| <= 2^-20, range 2^-19)
   layer-0 x: xh8 = xh*2^4 (|x| <= ~6, range 7.94); xl8 = (x-xh)*2^15
   layers>=1: xh8 = xh*2^8 (|x| <= ~0.12, range 0.496); xl8 = (x-xh)*2^19
   Cross-term product scale: qxh*qwl == qxl*qwh = 2^-30 (L0) / 2^-34 (L>=1)   */
#define QW_INV   32768.0f
#define QWL_INV  67108864.0f
#define QX0_INV  16.0f
#define QXL0_INV 32768.0f
#define QX_INV   256.0f
#define QXL_INV  524288.0f
#define QC0 9.313225746154785e-10f   /* 2^-30 */
#define QCN 5.820766091346741e-11f   /* 2^-34 */

// ---------------------------------------------------------------------------
// Scratch (allocation-free rule: __device__ globals)
// ---------------------------------------------------------------------------
__device__ __half g_Ahi[2][(size_t)BATCH * HID];
__device__ int8_t g_A8h[2][(size_t)BATCH * HID];
__device__ int8_t g_A8l[2][(size_t)BATCH * HID];
__device__ __half g_Whi[(size_t)NLAYERS * HID * HID];
__device__ int8_t g_W8h[(size_t)NLAYERS * HID * HID];
__device__ int8_t g_W8l[(size_t)NLAYERS * HID * HID];

// ---------------------------------------------------------------------------
// Helpers
// ---------------------------------------------------------------------------
__device__ __forceinline__ uint32_t smem_u32(const void* p) {
    uint32_t a;
    asm("{ .reg .u64 t; cvta.to.shared.u64 t, %1; cvt.u32.u64 %0, t; }"
        : "=r"(a) : "l"(p));
    return a;
}
__device__ __forceinline__ void ldm_x4(uint32_t addr, uint32_t r[4]) {
    asm volatile(
        "ldmatrix.sync.aligned.m8n8.x4.shared.b16 {%0,%1,%2,%3}, [%4];"
        : "=r"(r[0]), "=r"(r[1]), "=r"(r[2]), "=r"(r[3]) : "r"(addr));
}
__device__ __forceinline__ void mma16816(float c[4], const uint32_t a[4],
                                         const uint32_t b[2]) {
    asm volatile(
        "mma.sync.aligned.m16n8k16.row.col.f32.f16.f16.f32 "
        "{%0,%1,%2,%3}, {%4,%5,%6,%7}, {%8,%9}, {%0,%1,%2,%3};"
        : "+f"(c[0]), "+f"(c[1]), "+f"(c[2]), "+f"(c[3])
        : "r"(a[0]), "r"(a[1]), "r"(a[2]), "r"(a[3]), "r"(b[0]), "r"(b[1]));
}
__device__ __forceinline__ void imma16832(int32_t c[4], const uint32_t a[4],
                                          const uint32_t b[2]) {
    asm volatile(
        "mma.sync.aligned.m16n8k32.row.col.s32.s8.s8.s32 "
        "{%0,%1,%2,%3}, {%4,%5,%6,%7}, {%8,%9}, {%0,%1,%2,%3};"
        : "+r"(c[0]), "+r"(c[1]), "+r"(c[2]), "+r"(c[3])
        : "r"(a[0]), "r"(a[1]), "r"(a[2]), "r"(a[3]), "r"(b[0]), "r"(b[1]));
}
__device__ __forceinline__ int8_t q8(float v, float s) {
    float q = rintf(v * s);
    q = fminf(fmaxf(q, -127.0f), 127.0f);
    return (int8_t)(int)q;
}
#define CP_ASYNC16(sa, ga) \
    asm volatile("cp.async.cg.shared.global [%0], [%1], 16;" :: "r"(sa), "l"(ga))
#define CP_COMMIT() asm volatile("cp.async.commit_group;")
#define CP_WAIT1() asm volatile("cp.async.wait_group 1;")
#define CP_WAIT0() asm volatile("cp.async.wait_group 0;")

// ---------------------------------------------------------------------------
// Weight conversion: w_eff = w * WSCALE -> wh fp16, wh8 int8, wl8 int8
// ---------------------------------------------------------------------------
__global__ void wconv_kernel(const float* __restrict__ w,
                             __half* __restrict__ whi,
                             int8_t* __restrict__ w8h,
                             int8_t* __restrict__ w8l) {
    size_t i = (size_t)blockIdx.x * blockDim.x + threadIdx.x;
    float4 v = ((const float4*)w)[i];
    float e[4] = {v.x * WSCALE, v.y * WSCALE, v.z * WSCALE, v.w * WSCALE};
    union { uint2 u; __half h[4]; } ph;
    union { uint32_t u; int8_t b[4]; } p8h, p8l;
#pragma unroll
    for (int j = 0; j < 4; j++) {
        __half hh = __float2half_rn(e[j]);
        float hf = __half2float(hh);
        ph.h[j] = hh;
        p8h.b[j] = q8(hf, QW_INV);
        p8l.b[j] = q8(e[j] - hf, QWL_INV);
    }
    ((uint2*)whi)[i] = ph.u;
    ((uint32_t*)w8h)[i] = p8h.u;
    ((uint32_t*)w8l)[i] = p8l.u;
}

// ---------------------------------------------------------------------------
// Pixel norm -> xh fp16, xh8/xl8 int8 (layer-0 scales)
// ---------------------------------------------------------------------------
__global__ void pixelnorm_split_kernel(const float* __restrict__ z,
                                       __half* __restrict__ ahi,
                                       int8_t* __restrict__ a8h,
                                       int8_t* __restrict__ a8l) {
    const int row = blockIdx.x;
    const int tid = threadIdx.x;
    float4 v = ((const float4*)(z + (size_t)row * HID))[tid];
    float s = v.x * v.x + v.y * v.y + v.z * v.z + v.w * v.w;
#pragma unroll
    for (int o = 16; o > 0; o >>= 1) s += __shfl_xor_sync(0xffffffffu, s, o);
    __shared__ float ws[4];
    if ((tid & 31) == 0) ws[tid >> 5] = s;
    __syncthreads();
    float tot = ws[0] + ws[1] + ws[2] + ws[3];
    float r = rsqrtf(tot * (1.0f / HID) + EPSV);
    float e[4] = {v.x * r, v.y * r, v.z * r, v.w * r};
    union { uint2 u; __half h[4]; } ph;
    union { uint32_t u; int8_t b[4]; } p8h, p8l;
#pragma unroll
    for (int j = 0; j < 4; j++) {
        __half hh = __float2half_rn(e[j]);
        float hf = __half2float(hh);
        ph.h[j] = hh;
        p8h.b[j] = q8(hf, QX0_INV);
        p8l.b[j] = q8(e[j] - hf, QXL0_INV);
    }
    size_t off = ((size_t)row * HID) / 4 + tid;
    ((uint2*)ahi)[off] = ph.u;
    ((uint32_t*)a8h)[off] = p8h.u;
    ((uint32_t*)a8l)[off] = p8l.u;
}

// ---------------------------------------------------------------------------
// Hybrid GEMM layer: C = x @ w_eff^T via
//   fp16 HMMA: xh*wh  (fp32 accum)
//   int8 IMMA: xh8*wl8 + xl8*wh8 (shared s32 accum, common scale qc)
// Tile BM=128 x BN=64, BK=32, 256 threads (4m x 2n warps, 32x32 per warp),
// 2-stage cp.async, two-barrier ordering (proven R4/R5), 2 CTAs/SM.
// fp16 rows: 64 B data stride 80; int8 rows: 32 B data stride 48 (both
// conflict-free for ldmatrix).
// ---------------------------------------------------------------------------
#define RSTRIDE 80
#define R8STRIDE 48
#define OFF_AH 0                               /* 128*80  = 10240 */
#define OFF_BH 10240                           /*  64*80  =  5120 */
#define OFF_A8H 15360                          /* 128*48  =  6144 */
#define OFF_A8L 21504                          /* 128*48  =  6144 */
#define OFF_B8H 27648                          /*  64*48  =  3072 */
#define OFF_B8L 30720                          /*  64*48  =  3072 */
#define STAGE_BYTES 33792
#define SMEM_TOTAL (2 * STAGE_BYTES)           /* 67584 */

__device__ __forceinline__ void load_fp16A(uint32_t sbase,
                                           const __half* __restrict__ g,
                                           int rowbase, int kbase, int tid) {
#pragma unroll
    for (int h = 0; h < 2; h++) {
        int u = tid + h * 256;
        int row = u >> 2, un = u & 3;
        CP_ASYNC16(sbase + row * RSTRIDE + un * 16,
                   g + (size_t)(rowbase + row) * HID + kbase + un * 8);
    }
}
__device__ __forceinline__ void load_fp16B(uint32_t sbase,
                                           const __half* __restrict__ g,
                                           int rowbase, int kbase, int tid) {
    int row = tid >> 2, un = tid & 3;
    CP_ASYNC16(sbase + row * RSTRIDE + un * 16,
               g + (size_t)(rowbase + row) * HID + kbase + un * 8);
}
__device__ __forceinline__ void load_i8A(uint32_t sbase,
                                         const int8_t* __restrict__ g,
                                         int rowbase, int kbyte, int tid) {
    int row = tid >> 1, un = tid & 1;
    CP_ASYNC16(sbase + row * R8STRIDE + un * 16,
               g + (size_t)(rowbase + row) * HID + kbyte + un * 16);
}
__device__ __forceinline__ void load_i8B(uint32_t sbase,
                                         const int8_t* __restrict__ gh,
                                         const int8_t* __restrict__ gl,
                                         int rowbase, int kbyte, int tid) {
    int plane = tid >> 7, t = tid & 127;
    const int8_t* g = plane ? gl : gh;
    int row = t >> 1, un = t & 1;
    CP_ASYNC16(sbase + plane * 3072 + row * R8STRIDE + un * 16,
               g + (size_t)(rowbase + row) * HID + kbyte + un * 16);
}
__device__ __forceinline__ void load_stage(
    uint32_t sp, const __half* Ah, const int8_t* A8h, const int8_t* A8l,
    const __half* Wh, const int8_t* W8h, const int8_t* W8l, int bm, int bn,
    int kb, int tid) {
    load_fp16A(sp + OFF_AH, Ah, bm, kb, tid);
    load_fp16B(sp + OFF_BH, Wh, bn, kb, tid);
    load_i8A(sp + OFF_A8H, A8h, bm, kb, tid);
    load_i8A(sp + OFF_A8L, A8l, bm, kb, tid);
    load_i8B(sp + OFF_B8H, W8h, W8l, bn, kb, tid);
}

template <bool LAST>
__global__ __launch_bounds__(256, 2) void gemm_layer(
    const __half* __restrict__ Ahi, const int8_t* __restrict__ A8h,
    const int8_t* __restrict__ A8l, const __half* __restrict__ Whi,
    const int8_t* __restrict__ W8h, const int8_t* __restrict__ W8l,
    const float* __restrict__ bias, float qc, __half* __restrict__ Ohi,
    int8_t* __restrict__ O8h, int8_t* __restrict__ O8l,
    float* __restrict__ OutF) {
    extern __shared__ char smem[];
    const uint32_t sb = smem_u32(smem);
    const int tid = threadIdx.x;
    const int wid = tid >> 5;
    const int lid = tid & 31;
    const int wm = wid >> 1;            // 0..3 -> 32 rows each
    const int wn = wid & 1;             // 0..1 -> 32 cols each
    const int bm = blockIdx.y * 128;
    const int bn = blockIdx.x * 64;

    const int lt = lid >> 3;            // ldmatrix tile index 0..3
    const int li = lid & 7;

    // fp16 plane offsets
    const int am_row = wm * 32 + (lt & 1) * 8 + li;
    const int bn_row0 = wn * 32 + (lt >> 1) * 8 + li;
    uint32_t aoff[2], boff[2];
#pragma unroll
    for (int mf = 0; mf < 2; mf++)
        aoff[mf] = OFF_AH + (am_row + mf * 16) * RSTRIDE + (lt >> 1) * 16;
#pragma unroll
    for (int p = 0; p < 2; p++)
        boff[p] = OFF_BH + (bn_row0 + p * 16) * RSTRIDE + (lt & 1) * 16;
    // int8 plane offsets (same lane geometry, 16B k-halves of a 32B row)
    uint32_t a8off[2], b8off[2];
#pragma unroll
    for (int mf = 0; mf < 2; mf++)
        a8off[mf] = OFF_A8H + (am_row + mf * 16) * R8STRIDE + (lt >> 1) * 16;
#pragma unroll
    for (int p = 0; p < 2; p++)
        b8off[p] = OFF_B8H + (bn_row0 + p * 16) * R8STRIDE + (lt & 1) * 16;

    float accf[2][4][4];
    int32_t accs[2][4][4];
#pragma unroll
    for (int a = 0; a < 2; a++)
#pragma unroll
        for (int b = 0; b < 4; b++)
#pragma unroll
            for (int c = 0; c < 4; c++) { accf[a][b][c] = 0.0f; accs[a][b][c] = 0; }

    load_stage(sb, Ahi, A8h, A8l, Whi, W8h, W8l, bm, bn, 0, tid);
    CP_COMMIT();

    for (int s = 0; s < 16; s++) {
        if (s + 1 < 16) {
            uint32_t sn = sb + ((s + 1) & 1) * STAGE_BYTES;
            load_stage(sn, Ahi, A8h, A8l, Whi, W8h, W8l, bm, bn, (s + 1) * 32,
                       tid);
            CP_COMMIT();
            CP_WAIT1();
        } else {
            CP_WAIT0();
        }
        __syncthreads();

        uint32_t sc = sb + (s & 1) * STAGE_BYTES;

        // ---- fp16 term: xh * wh ----
#pragma unroll
        for (int kk = 0; kk < 2; kk++) {
            uint32_t ah[2][4];
#pragma unroll
            for (int mf = 0; mf < 2; mf++)
                ldm_x4(sc + aoff[mf] + kk * 32, ah[mf]);
            uint32_t bh[4][2];
#pragma unroll
            for (int p = 0; p < 2; p++) {
                uint32_t r[4];
                ldm_x4(sc + boff[p] + kk * 32, r);
                bh[2 * p][0] = r[0]; bh[2 * p][1] = r[1];
                bh[2 * p + 1][0] = r[2]; bh[2 * p + 1][1] = r[3];
            }
#pragma unroll
            for (int mf = 0; mf < 2; mf++)
#pragma unroll
                for (int nf = 0; nf < 4; nf++)
                    mma16816(accf[mf][nf], ah[mf], bh[nf]);
        }

        // ---- int8 term 2: xh8 * wl8 ----
        {
            uint32_t xa[2][4], wb[4][2];
#pragma unroll
            for (int mf = 0; mf < 2; mf++)
                ldm_x4(sc + a8off[mf], xa[mf]);
#pragma unroll
            for (int p = 0; p < 2; p++) {
                uint32_t r[4];
                ldm_x4(sc + b8off[p] + 3072, r);   /* OFF_B8L plane */
                wb[2 * p][0] = r[0]; wb[2 * p][1] = r[1];
                wb[2 * p + 1][0] = r[2]; wb[2 * p + 1][1] = r[3];
            }
#pragma unroll
            for (int mf = 0; mf < 2; mf++)
#pragma unroll
                for (int nf = 0; nf < 4; nf++)
                    imma16832(accs[mf][nf], xa[mf], wb[nf]);
        }
        // ---- int8 term 3: xl8 * wh8 ----
        {
            uint32_t xa[2][4], wb[4][2];
#pragma unroll
            for (int mf = 0; mf < 2; mf++)
                ldm_x4(sc + a8off[mf] + 6144, xa[mf]);   /* OFF_A8L plane */
#pragma unroll
            for (int p = 0; p < 2; p++) {
                uint32_t r[4];
                ldm_x4(sc + b8off[p], r);                /* OFF_B8H plane */
                wb[2 * p][0] = r[0]; wb[2 * p][1] = r[1];
                wb[2 * p + 1][0] = r[2]; wb[2 * p + 1][1] = r[3];
            }
#pragma unroll
            for (int mf = 0; mf < 2; mf++)
#pragma unroll
                for (int nf = 0; nf < 4; nf++)
                    imma16832(accs[mf][nf], xa[mf], wb[nf]);
        }
        __syncthreads();
    }

    // Epilogue: m16n8 c mapping: reg e -> row=(l/4)+(e>=2?8:0), col=(l%4)*2+(e&1)
    float bj[4][2];
#pragma unroll
    for (int nf = 0; nf < 4; nf++) {
        int col = bn + wn * 32 + nf * 8 + (lid & 3) * 2;
        bj[nf][0] = bias[col] * BSCALE;
        bj[nf][1] = bias[col + 1] * BSCALE;
    }

#pragma unroll
    for (int mf = 0; mf < 2; mf++) {
#pragma unroll
        for (int half_ : {0, 1}) {
            int row = bm + wm * 32 + mf * 16 + (lid >> 2) + half_ * 8;
#pragma unroll
            for (int nf = 0; nf < 4; nf++) {
                int col = bn + wn * 32 + nf * 8 + (lid & 3) * 2;
                int e0 = half_ * 2, e1 = half_ * 2 + 1;
                float x0 = accf[mf][nf][e0] + (float)accs[mf][nf][e0] * qc +
                           bj[nf][0];
                float x1 = accf[mf][nf][e1] + (float)accs[mf][nf][e1] * qc +
                           bj[nf][1];
                x0 = (x0 > 0.0f ? x0 : SLOPE * x0) * GAIN;
                x1 = (x1 > 0.0f ? x1 : SLOPE * x1) * GAIN;
                if (!LAST) {
                    __half h0 = __float2half_rn(x0);
                    __half h1 = __float2half_rn(x1);
                    float h0f = __half2float(h0), h1f = __half2float(h1);
                    size_t off = (size_t)row * HID + col;
                    *(__half2*)(Ohi + off) = __halves2half2(h0, h1);
                    union { short s; int8_t b[2]; } ph, pl;
                    ph.b[0] = q8(h0f, QX_INV);
                    ph.b[1] = q8(h1f, QX_INV);
                    pl.b[0] = q8(x0 - h0f, QXL_INV);
                    pl.b[1] = q8(x1 - h1f, QXL_INV);
                    *(short*)(O8h + off) = ph.s;
                    *(short*)(O8l + off) = pl.s;
                } else {
                    float2 p = make_float2(x0, x1);
#pragma unroll
                    for (int r = 0; r < NOUT; r++) {
                        size_t off = ((size_t)row * NOUT + r) * HID + col;
                        *(float2*)(OutF + off) = p;
                    }
                }
            }
        }
    }
}

// ---------------------------------------------------------------------------
extern "C" void kernel_launch(void* const* d_in, const int* in_sizes, int n_in,
                              void* d_out, int out_size) {
    const float* z = (const float*)d_in[0];
    const float* weight = (const float*)d_in[1];
    const float* bias = (const float*)d_in[2];
    float* out = (float*)d_out;

    __half *ahi, *whi;
    int8_t *a8h, *a8l, *w8h, *w8l;
    cudaGetSymbolAddress((void**)&ahi, g_Ahi);
    cudaGetSymbolAddress((void**)&a8h, g_A8h);
    cudaGetSymbolAddress((void**)&a8l, g_A8l);
    cudaGetSymbolAddress((void**)&whi, g_Whi);
    cudaGetSymbolAddress((void**)&w8h, g_W8h);
    cudaGetSymbolAddress((void**)&w8l, g_W8l);

    cudaFuncSetAttribute(gemm_layer<false>,
                         cudaFuncAttributeMaxDynamicSharedMemorySize, SMEM_TOTAL);
    cudaFuncSetAttribute(gemm_layer<true>,
                         cudaFuncAttributeMaxDynamicSharedMemorySize, SMEM_TOTAL);

    wconv_kernel<<<2048, 256>>>(weight, whi, w8h, w8l);
    pixelnorm_split_kernel<<<BATCH, 128>>>(z, ahi, a8h, a8l);

    const size_t ABUF = (size_t)BATCH * HID;
    const size_t WBUF = (size_t)HID * HID;
    dim3 grid(HID / 64, BATCH / 128);   // (8, 128) = 1024 CTAs
    for (int l = 0; l < NLAYERS; l++) {
        int pi = l & 1, po = (l + 1) & 1;
        const __half* Ah = ahi + pi * ABUF;
        const int8_t* Xh = a8h + pi * ABUF;
        const int8_t* Xl = a8l + pi * ABUF;
        __half* Oh = ahi + po * ABUF;
        int8_t* Yh = a8h + po * ABUF;
        int8_t* Yl = a8l + po * ABUF;
        const __half* Wh = whi + (size_t)l * WBUF;
        const int8_t* Wq = w8h + (size_t)l * WBUF;
        const int8_t* Wr = w8l + (size_t)l * WBUF;
        const float* bl = bias + (size_t)l * HID;
        float qc = (l == 0) ? QC0 : QCN;
        if (l == NLAYERS - 1)
            gemm_layer<true><<<grid, 256, SMEM_TOTAL>>>(
                Ah, Xh, Xl, Wh, Wq, Wr, bl, qc, nullptr, nullptr, nullptr, out);
        else
            gemm_layer<false><<<grid, 256, SMEM_TOTAL>>>(
                Ah, Xh, Xl, Wh, Wq, Wr, bl, qc, Oh, Yh, Yl, nullptr);
    }
}

// round 11
// speedup vs baseline: 3.9830x; 3.9830x over previous
#include <cuda_runtime.h>
#include <cuda_fp16.h>
#include <cstdint>

#define BATCH   16384
#define HID     512
#define NLAYERS 8
#define NOUT    16
#define WSCALE  4.4194173824159215e-04f  /* 0.01 / sqrt(512) */
#define BSCALE  0.01f
#define SLOPE   0.2f
#define GAIN    1.41421356237f
#define EPSV    1e-8f

// ---------------------------------------------------------------------------
// Scratch (allocation-free rule: __device__ globals)
// ---------------------------------------------------------------------------
__device__ __half g_A[2][(size_t)BATCH * HID];
__device__ __half g_W[(size_t)NLAYERS * HID * HID];

// ---------------------------------------------------------------------------
// Helpers
// ---------------------------------------------------------------------------
__device__ __forceinline__ uint32_t smem_u32(const void* p) {
    uint32_t a;
    asm("{ .reg .u64 t; cvta.to.shared.u64 t, %1; cvt.u32.u64 %0, t; }"
        : "=r"(a) : "l"(p));
    return a;
}
__device__ __forceinline__ void ldm_x4(uint32_t addr, uint32_t r[4]) {
    asm volatile(
        "ldmatrix.sync.aligned.m8n8.x4.shared.b16 {%0,%1,%2,%3}, [%4];"
        : "=r"(r[0]), "=r"(r[1]), "=r"(r[2]), "=r"(r[3]) : "r"(addr));
}
__device__ __forceinline__ void mma16816(float c[4], const uint32_t a[4],
                                         const uint32_t b[2]) {
    asm volatile(
        "mma.sync.aligned.m16n8k16.row.col.f32.f16.f16.f32 "
        "{%0,%1,%2,%3}, {%4,%5,%6,%7}, {%8,%9}, {%0,%1,%2,%3};"
        : "+f"(c[0]), "+f"(c[1]), "+f"(c[2]), "+f"(c[3])
        : "r"(a[0]), "r"(a[1]), "r"(a[2]), "r"(a[3]), "r"(b[0]), "r"(b[1]));
}
#define CP_ASYNC16(sa, ga) \
    asm volatile("cp.async.cg.shared.global [%0], [%1], 16;" :: "r"(sa), "l"(ga))
#define CP_COMMIT() asm volatile("cp.async.commit_group;")
#define CP_WAIT1() asm volatile("cp.async.wait_group 1;")
#define CP_WAIT0() asm volatile("cp.async.wait_group 0;")

// ---------------------------------------------------------------------------
// Weight conversion: w_eff = w * WSCALE -> fp16
// ---------------------------------------------------------------------------
__global__ void wconv_kernel(const float* __restrict__ w,
                             __half* __restrict__ wh) {
    size_t i = (size_t)blockIdx.x * blockDim.x + threadIdx.x;
    float4 v = ((const float4*)w)[i];
    union { uint2 u; __half h[4]; } ph;
    ph.h[0] = __float2half_rn(v.x * WSCALE);
    ph.h[1] = __float2half_rn(v.y * WSCALE);
    ph.h[2] = __float2half_rn(v.z * WSCALE);
    ph.h[3] = __float2half_rn(v.w * WSCALE);
    ((uint2*)wh)[i] = ph.u;
}

// ---------------------------------------------------------------------------
// Pixel norm -> fp16
// ---------------------------------------------------------------------------
__global__ void pixelnorm_kernel(const float* __restrict__ z,
                                 __half* __restrict__ a) {
    const int row = blockIdx.x;
    const int tid = threadIdx.x;
    float4 v = ((const float4*)(z + (size_t)row * HID))[tid];
    float s = v.x * v.x + v.y * v.y + v.z * v.z + v.w * v.w;
#pragma unroll
    for (int o = 16; o > 0; o >>= 1) s += __shfl_xor_sync(0xffffffffu, s, o);
    __shared__ float ws[4];
    if ((tid & 31) == 0) ws[tid >> 5] = s;
    __syncthreads();
    float tot = ws[0] + ws[1] + ws[2] + ws[3];
    float r = rsqrtf(tot * (1.0f / HID) + EPSV);
    union { uint2 u; __half h[4]; } ph;
    ph.h[0] = __float2half_rn(v.x * r);
    ph.h[1] = __float2half_rn(v.y * r);
    ph.h[2] = __float2half_rn(v.z * r);
    ph.h[3] = __float2half_rn(v.w * r);
    ((uint2*)a)[((size_t)row * HID) / 4 + tid] = ph.u;
}

// ---------------------------------------------------------------------------
// Single-term fp16 HMMA GEMM layer.  C[m,n] = sum_k a[m,k] * w_eff[n,k]
// Tile BM=128 x BN=64, BK=32, 256 threads (4m x 2n warps, 32x32 per warp),
// 2-stage cp.async, two-barrier ordering (proven R4/R5), 3 CTAs/SM.
// SMEM rows: 32 half = 64 B data, stride 80 B (conflict-free ldmatrix).
// ---------------------------------------------------------------------------
#define RSTRIDE 80
#define A_TILE_BYTES (128 * RSTRIDE)     /* 10240 */
#define B_TILE_BYTES (64 * RSTRIDE)      /* 5120 */
#define STAGE_BYTES (A_TILE_BYTES + B_TILE_BYTES) /* 15360 */
#define SMEM_TOTAL (2 * STAGE_BYTES)     /* 30720 */
#define OFF_A 0
#define OFF_B A_TILE_BYTES

__device__ __forceinline__ void load_stage(uint32_t sp,
                                           const __half* __restrict__ A,
                                           const __half* __restrict__ W,
                                           int bm, int bn, int kb, int tid) {
    // A: 128 rows x 4 units = 512 cp.async (2/thread)
#pragma unroll
    for (int h = 0; h < 2; h++) {
        int u = tid + h * 256;
        int row = u >> 2, un = u & 3;
        CP_ASYNC16(sp + OFF_A + row * RSTRIDE + un * 16,
                   A + (size_t)(bm + row) * HID + kb + un * 8);
    }
    // B: 64 rows x 4 units = 256 cp.async (1/thread)
    {
        int row = tid >> 2, un = tid & 3;
        CP_ASYNC16(sp + OFF_B + row * RSTRIDE + un * 16,
                   W + (size_t)(bn + row) * HID + kb + un * 8);
    }
}

template <bool LAST>
__global__ __launch_bounds__(256, 3) void gemm_layer(
    const __half* __restrict__ A, const __half* __restrict__ W,
    const float* __restrict__ bias, __half* __restrict__ O,
    float* __restrict__ OutF) {
    extern __shared__ char smem[];
    const uint32_t sb = smem_u32(smem);
    const int tid = threadIdx.x;
    const int wid = tid >> 5;
    const int lid = tid & 31;
    const int wm = wid >> 1;            // 0..3 -> 32 rows each
    const int wn = wid & 1;             // 0..1 -> 32 cols each
    const int bm = blockIdx.y * 128;
    const int bn = blockIdx.x * 64;

    const int lt = lid >> 3;            // ldmatrix tile index 0..3
    const int li = lid & 7;

    const int am_row = wm * 32 + (lt & 1) * 8 + li;
    const int bn_row0 = wn * 32 + (lt >> 1) * 8 + li;
    uint32_t aoff[2], boff[2];
#pragma unroll
    for (int mf = 0; mf < 2; mf++)
        aoff[mf] = OFF_A + (am_row + mf * 16) * RSTRIDE + (lt >> 1) * 16;
#pragma unroll
    for (int p = 0; p < 2; p++)
        boff[p] = OFF_B + (bn_row0 + p * 16) * RSTRIDE + (lt & 1) * 16;

    float acc[2][4][4];
#pragma unroll
    for (int a = 0; a < 2; a++)
#pragma unroll
        for (int b = 0; b < 4; b++)
#pragma unroll
            for (int c = 0; c < 4; c++) acc[a][b][c] = 0.0f;

    load_stage(sb, A, W, bm, bn, 0, tid);
    CP_COMMIT();

    for (int s = 0; s < 16; s++) {
        if (s + 1 < 16) {
            load_stage(sb + ((s + 1) & 1) * STAGE_BYTES, A, W, bm, bn,
                       (s + 1) * 32, tid);
            CP_COMMIT();
            CP_WAIT1();
        } else {
            CP_WAIT0();
        }
        __syncthreads();

        uint32_t sc = sb + (s & 1) * STAGE_BYTES;
#pragma unroll
        for (int kk = 0; kk < 2; kk++) {
            uint32_t ah[2][4];
#pragma unroll
            for (int mf = 0; mf < 2; mf++)
                ldm_x4(sc + aoff[mf] + kk * 32, ah[mf]);
            uint32_t bh[4][2];
#pragma unroll
            for (int p = 0; p < 2; p++) {
                uint32_t r[4];
                ldm_x4(sc + boff[p] + kk * 32, r);
                bh[2 * p][0] = r[0]; bh[2 * p][1] = r[1];
                bh[2 * p + 1][0] = r[2]; bh[2 * p + 1][1] = r[3];
            }
#pragma unroll
            for (int mf = 0; mf < 2; mf++)
#pragma unroll
                for (int nf = 0; nf < 4; nf++)
                    mma16816(acc[mf][nf], ah[mf], bh[nf]);
        }
        __syncthreads();
    }

    // Epilogue: m16n8 c mapping: reg e -> row=(l/4)+(e>=2?8:0), col=(l%4)*2+(e&1)
    float bj[4][2];
#pragma unroll
    for (int nf = 0; nf < 4; nf++) {
        int col = bn + wn * 32 + nf * 8 + (lid & 3) * 2;
        bj[nf][0] = bias[col] * BSCALE;
        bj[nf][1] = bias[col + 1] * BSCALE;
    }

#pragma unroll
    for (int mf = 0; mf < 2; mf++) {
#pragma unroll
        for (int half_ : {0, 1}) {
            int row = bm + wm * 32 + mf * 16 + (lid >> 2) + half_ * 8;
#pragma unroll
            for (int nf = 0; nf < 4; nf++) {
                int col = bn + wn * 32 + nf * 8 + (lid & 3) * 2;
                float x0 = acc[mf][nf][half_ * 2 + 0] + bj[nf][0];
                float x1 = acc[mf][nf][half_ * 2 + 1] + bj[nf][1];
                x0 = (x0 > 0.0f ? x0 : SLOPE * x0) * GAIN;
                x1 = (x1 > 0.0f ? x1 : SLOPE * x1) * GAIN;
                if (!LAST) {
                    size_t off = (size_t)row * HID + col;
                    *(__half2*)(O + off) =
                        __halves2half2(__float2half_rn(x0), __float2half_rn(x1));
                } else {
                    float2 p = make_float2(x0, x1);
#pragma unroll
                    for (int r = 0; r < NOUT; r++) {
                        size_t off = ((size_t)row * NOUT + r) * HID + col;
                        *(float2*)(OutF + off) = p;
                    }
                }
            }
        }
    }
}

// ---------------------------------------------------------------------------
extern "C" void kernel_launch(void* const* d_in, const int* in_sizes, int n_in,
                              void* d_out, int out_size) {
    const float* z = (const float*)d_in[0];
    const float* weight = (const float*)d_in[1];
    const float* bias = (const float*)d_in[2];
    float* out = (float*)d_out;

    __half *a, *w;
    cudaGetSymbolAddress((void**)&a, g_A);
    cudaGetSymbolAddress((void**)&w, g_W);

    cudaFuncSetAttribute(gemm_layer<false>,
                         cudaFuncAttributeMaxDynamicSharedMemorySize, SMEM_TOTAL);
    cudaFuncSetAttribute(gemm_layer<true>,
                         cudaFuncAttributeMaxDynamicSharedMemorySize, SMEM_TOTAL);

    wconv_kernel<<<2048, 256>>>(weight, w);
    pixelnorm_kernel<<<BATCH, 128>>>(z, a);

    const size_t ABUF = (size_t)BATCH * HID;
    const size_t WBUF = (size_t)HID * HID;
    dim3 grid(HID / 64, BATCH / 128);   // (8, 128) = 1024 CTAs
    for (int l = 0; l < NLAYERS; l++) {
        const __half* Ain = a + (l & 1) * ABUF;
        __half* Aout = a + ((l + 1) & 1) * ABUF;
        const __half* Wl = w + (size_t)l * WBUF;
        const float* bl = bias + (size_t)l * HID;
        if (l == NLAYERS - 1)
            gemm_layer<true><<<grid, 256, SMEM_TOTAL>>>(Ain, Wl, bl, nullptr,
                                                        out);
        else
            gemm_layer<false><<<grid, 256, SMEM_TOTAL>>>(Ain, Wl, bl, Aout,
                                                         nullptr);
    }
}

// round 12
// speedup vs baseline: 4.3327x; 1.0878x over previous
#include <cuda_runtime.h>
#include <cuda_fp16.h>
#include <cstdint>

#define BATCH   16384
#define HID     512
#define NLAYERS 8
#define NOUT    16
#define WSCALE  4.4194173824159215e-04f  /* 0.01 / sqrt(512) */
#define BSCALE  0.01f
#define SLOPE   0.2f
#define GAIN    1.41421356237f
#define EPSV    1e-8f

// ---------------------------------------------------------------------------
// Scratch (allocation-free rule: __device__ globals)
// ---------------------------------------------------------------------------
__device__ __half g_A[2][(size_t)BATCH * HID];
__device__ __half g_W[(size_t)NLAYERS * HID * HID];

// ---------------------------------------------------------------------------
// Helpers
// ---------------------------------------------------------------------------
__device__ __forceinline__ uint32_t smem_u32(const void* p) {
    uint32_t a;
    asm("{ .reg .u64 t; cvta.to.shared.u64 t, %1; cvt.u32.u64 %0, t; }"
        : "=r"(a) : "l"(p));
    return a;
}
__device__ __forceinline__ void ldm_x4(uint32_t addr, uint32_t r[4]) {
    asm volatile(
        "ldmatrix.sync.aligned.m8n8.x4.shared.b16 {%0,%1,%2,%3}, [%4];"
        : "=r"(r[0]), "=r"(r[1]), "=r"(r[2]), "=r"(r[3]) : "r"(addr));
}
__device__ __forceinline__ void mma16816(float c[4], const uint32_t a[4],
                                         const uint32_t b[2]) {
    asm volatile(
        "mma.sync.aligned.m16n8k16.row.col.f32.f16.f16.f32 "
        "{%0,%1,%2,%3}, {%4,%5,%6,%7}, {%8,%9}, {%0,%1,%2,%3};"
        : "+f"(c[0]), "+f"(c[1]), "+f"(c[2]), "+f"(c[3])
        : "r"(a[0]), "r"(a[1]), "r"(a[2]), "r"(a[3]), "r"(b[0]), "r"(b[1]));
}
#define CP_ASYNC16(sa, ga) \
    asm volatile("cp.async.cg.shared.global [%0], [%1], 16;" :: "r"(sa), "l"(ga))
#define CP_COMMIT() asm volatile("cp.async.commit_group;")
#define CP_WAIT1() asm volatile("cp.async.wait_group 1;")
#define CP_WAIT0() asm volatile("cp.async.wait_group 0;")

// ---------------------------------------------------------------------------
// Weight conversion: w_eff = w * WSCALE -> fp16
// ---------------------------------------------------------------------------
__global__ void wconv_kernel(const float* __restrict__ w,
                             __half* __restrict__ wh) {
    size_t i = (size_t)blockIdx.x * blockDim.x + threadIdx.x;
    float4 v = ((const float4*)w)[i];
    union { uint2 u; __half h[4]; } ph;
    ph.h[0] = __float2half_rn(v.x * WSCALE);
    ph.h[1] = __float2half_rn(v.y * WSCALE);
    ph.h[2] = __float2half_rn(v.z * WSCALE);
    ph.h[3] = __float2half_rn(v.w * WSCALE);
    ((uint2*)wh)[i] = ph.u;
}

// ---------------------------------------------------------------------------
// Pixel norm -> fp16
// ---------------------------------------------------------------------------
__global__ void pixelnorm_kernel(const float* __restrict__ z,
                                 __half* __restrict__ a) {
    const int row = blockIdx.x;
    const int tid = threadIdx.x;
    float4 v = ((const float4*)(z + (size_t)row * HID))[tid];
    float s = v.x * v.x + v.y * v.y + v.z * v.z + v.w * v.w;
#pragma unroll
    for (int o = 16; o > 0; o >>= 1) s += __shfl_xor_sync(0xffffffffu, s, o);
    __shared__ float ws[4];
    if ((tid & 31) == 0) ws[tid >> 5] = s;
    __syncthreads();
    float tot = ws[0] + ws[1] + ws[2] + ws[3];
    float r = rsqrtf(tot * (1.0f / HID) + EPSV);
    union { uint2 u; __half h[4]; } ph;
    ph.h[0] = __float2half_rn(v.x * r);
    ph.h[1] = __float2half_rn(v.y * r);
    ph.h[2] = __float2half_rn(v.z * r);
    ph.h[3] = __float2half_rn(v.w * r);
    ((uint2*)a)[((size_t)row * HID) / 4 + tid] = ph.u;
}

// ---------------------------------------------------------------------------
// Single-term fp16 HMMA GEMM layer.  C[m,n] = sum_k a[m,k] * w_eff[n,k]
// Tile BM=128 x BN=128, BK=32, 128 threads (2m x 2n warps), warp tile 64x64
// -> 128 LDSM-bytes per MMA (halves the smem crossbar demand that bound
// R11), 2-stage cp.async, two-barrier ordering (proven), 2 CTAs/SM.
// SMEM rows: 32 half = 64 B data, stride 80 B (conflict-free ldmatrix).
// ---------------------------------------------------------------------------
#define RSTRIDE 80
#define PLANE_BYTES (128 * RSTRIDE)      /* 10240 */
#define STAGE_BYTES (2 * PLANE_BYTES)    /* 20480 */
#define SMEM_TOTAL (2 * STAGE_BYTES)     /* 40960 */
#define OFF_A 0
#define OFF_B PLANE_BYTES

__device__ __forceinline__ void load_stage(uint32_t sp,
                                           const __half* __restrict__ A,
                                           const __half* __restrict__ W,
                                           int bm, int bn, int kb, int tid) {
    // A plane: 128 rows x 4 units = 512 cp.async (4/thread)
#pragma unroll
    for (int h = 0; h < 4; h++) {
        int u = tid + h * 128;
        int row = u >> 2, un = u & 3;
        CP_ASYNC16(sp + OFF_A + row * RSTRIDE + un * 16,
                   A + (size_t)(bm + row) * HID + kb + un * 8);
    }
    // B plane: 128 rows x 4 units = 512 cp.async (4/thread)
#pragma unroll
    for (int h = 0; h < 4; h++) {
        int u = tid + h * 128;
        int row = u >> 2, un = u & 3;
        CP_ASYNC16(sp + OFF_B + row * RSTRIDE + un * 16,
                   W + (size_t)(bn + row) * HID + kb + un * 8);
    }
}

template <bool LAST>
__global__ __launch_bounds__(128, 2) void gemm_layer(
    const __half* __restrict__ A, const __half* __restrict__ W,
    const float* __restrict__ bias, __half* __restrict__ O,
    float* __restrict__ OutF) {
    extern __shared__ char smem[];
    const uint32_t sb = smem_u32(smem);
    const int tid = threadIdx.x;
    const int wid = tid >> 5;
    const int lid = tid & 31;
    const int wm = wid >> 1;            // 0..1 -> 64 rows each
    const int wn = wid & 1;             // 0..1 -> 64 cols each
    const int bm = blockIdx.y * 128;
    const int bn = blockIdx.x * 128;

    const int lt = lid >> 3;            // ldmatrix tile index 0..3
    const int li = lid & 7;

    const int am_row = wm * 64 + (lt & 1) * 8 + li;
    const int bn_row0 = wn * 64 + (lt >> 1) * 8 + li;
    uint32_t aoff[4], boff[4];
#pragma unroll
    for (int mf = 0; mf < 4; mf++)
        aoff[mf] = OFF_A + (am_row + mf * 16) * RSTRIDE + (lt >> 1) * 16;
#pragma unroll
    for (int p = 0; p < 4; p++)
        boff[p] = OFF_B + (bn_row0 + p * 16) * RSTRIDE + (lt & 1) * 16;

    float acc[4][8][4];
#pragma unroll
    for (int a = 0; a < 4; a++)
#pragma unroll
        for (int b = 0; b < 8; b++)
#pragma unroll
            for (int c = 0; c < 4; c++) acc[a][b][c] = 0.0f;

    load_stage(sb, A, W, bm, bn, 0, tid);
    CP_COMMIT();

    for (int s = 0; s < 16; s++) {
        if (s + 1 < 16) {
            load_stage(sb + ((s + 1) & 1) * STAGE_BYTES, A, W, bm, bn,
                       (s + 1) * 32, tid);
            CP_COMMIT();
            CP_WAIT1();
        } else {
            CP_WAIT0();
        }
        __syncthreads();

        uint32_t sc = sb + (s & 1) * STAGE_BYTES;
#pragma unroll
        for (int kk = 0; kk < 2; kk++) {
            uint32_t ah[4][4];
#pragma unroll
            for (int mf = 0; mf < 4; mf++)
                ldm_x4(sc + aoff[mf] + kk * 32, ah[mf]);
            uint32_t bh[8][2];
#pragma unroll
            for (int p = 0; p < 4; p++) {
                uint32_t r[4];
                ldm_x4(sc + boff[p] + kk * 32, r);
                bh[2 * p][0] = r[0]; bh[2 * p][1] = r[1];
                bh[2 * p + 1][0] = r[2]; bh[2 * p + 1][1] = r[3];
            }
#pragma unroll
            for (int mf = 0; mf < 4; mf++)
#pragma unroll
                for (int nf = 0; nf < 8; nf++)
                    mma16816(acc[mf][nf], ah[mf], bh[nf]);
        }
        __syncthreads();
    }

    // Epilogue: m16n8 c mapping: reg e -> row=(l/4)+(e>=2?8:0), col=(l%4)*2+(e&1)
    float bj[8][2];
#pragma unroll
    for (int nf = 0; nf < 8; nf++) {
        int col = bn + wn * 64 + nf * 8 + (lid & 3) * 2;
        bj[nf][0] = bias[col] * BSCALE;
        bj[nf][1] = bias[col + 1] * BSCALE;
    }

#pragma unroll
    for (int mf = 0; mf < 4; mf++) {
#pragma unroll
        for (int half_ : {0, 1}) {
            int row = bm + wm * 64 + mf * 16 + (lid >> 2) + half_ * 8;
#pragma unroll
            for (int nf = 0; nf < 8; nf++) {
                int col = bn + wn * 64 + nf * 8 + (lid & 3) * 2;
                float x0 = acc[mf][nf][half_ * 2 + 0] + bj[nf][0];
                float x1 = acc[mf][nf][half_ * 2 + 1] + bj[nf][1];
                x0 = (x0 > 0.0f ? x0 : SLOPE * x0) * GAIN;
                x1 = (x1 > 0.0f ? x1 : SLOPE * x1) * GAIN;
                if (!LAST) {
                    size_t off = (size_t)row * HID + col;
                    *(__half2*)(O + off) =
                        __halves2half2(__float2half_rn(x0), __float2half_rn(x1));
                } else {
                    float2 p = make_float2(x0, x1);
#pragma unroll
                    for (int r = 0; r < NOUT; r++) {
                        size_t off = ((size_t)row * NOUT + r) * HID + col;
                        *(float2*)(OutF + off) = p;
                    }
                }
            }
        }
    }
}

// ---------------------------------------------------------------------------
extern "C" void kernel_launch(void* const* d_in, const int* in_sizes, int n_in,
                              void* d_out, int out_size) {
    const float* z = (const float*)d_in[0];
    const float* weight = (const float*)d_in[1];
    const float* bias = (const float*)d_in[2];
    float* out = (float*)d_out;

    __half *a, *w;
    cudaGetSymbolAddress((void**)&a, g_A);
    cudaGetSymbolAddress((void**)&w, g_W);

    cudaFuncSetAttribute(gemm_layer<false>,
                         cudaFuncAttributeMaxDynamicSharedMemorySize, SMEM_TOTAL);
    cudaFuncSetAttribute(gemm_layer<true>,
                         cudaFuncAttributeMaxDynamicSharedMemorySize, SMEM_TOTAL);

    wconv_kernel<<<2048, 256>>>(weight, w);
    pixelnorm_kernel<<<BATCH, 128>>>(z, a);

    const size_t ABUF = (size_t)BATCH * HID;
    const size_t WBUF = (size_t)HID * HID;
    dim3 grid(HID / 128, BATCH / 128);  // (4, 128) = 512 CTAs
    for (int l = 0; l < NLAYERS; l++) {
        const __half* Ain = a + (l & 1) * ABUF;
        __half* Aout = a + ((l + 1) & 1) * ABUF;
        const __half* Wl = w + (size_t)l * WBUF;
        const float* bl = bias + (size_t)l * HID;
        if (l == NLAYERS - 1)
            gemm_layer<true><<<grid, 128, SMEM_TOTAL>>>(Ain, Wl, bl, nullptr,
                                                        out);
        else
            gemm_layer<false><<<grid, 128, SMEM_TOTAL>>>(Ain, Wl, bl, Aout,
                                                         nullptr);
    }
}

// round 13
// speedup vs baseline: 4.6301x; 1.0686x over previous
#include <cuda_runtime.h>
#include <cuda_fp16.h>
#include <cstdint>

#define BATCH   16384
#define HID     512
#define NLAYERS 8
#define NOUT    16
#define WSCALE  4.4194173824159215e-04f  /* 0.01 / sqrt(512) */
#define BSCALE  0.01f
#define SLOPE   0.2f
#define GAIN    1.41421356237f
#define EPSV    1e-8f

// ---------------------------------------------------------------------------
// Scratch (allocation-free rule: __device__ globals)
// ---------------------------------------------------------------------------
__device__ __half g_A[2][(size_t)BATCH * HID];
__device__ __half g_W[(size_t)NLAYERS * HID * HID];

// ---------------------------------------------------------------------------
// Helpers
// ---------------------------------------------------------------------------
__device__ __forceinline__ uint32_t smem_u32(const void* p) {
    uint32_t a;
    asm("{ .reg .u64 t; cvta.to.shared.u64 t, %1; cvt.u32.u64 %0, t; }"
        : "=r"(a) : "l"(p));
    return a;
}
__device__ __forceinline__ void ldm_x4(uint32_t addr, uint32_t r[4]) {
    asm volatile(
        "ldmatrix.sync.aligned.m8n8.x4.shared.b16 {%0,%1,%2,%3}, [%4];"
        : "=r"(r[0]), "=r"(r[1]), "=r"(r[2]), "=r"(r[3]) : "r"(addr));
}
__device__ __forceinline__ void mma16816(float c[4], const uint32_t a[4],
                                         const uint32_t b[2]) {
    asm volatile(
        "mma.sync.aligned.m16n8k16.row.col.f32.f16.f16.f32 "
        "{%0,%1,%2,%3}, {%4,%5,%6,%7}, {%8,%9}, {%0,%1,%2,%3};"
        : "+f"(c[0]), "+f"(c[1]), "+f"(c[2]), "+f"(c[3])
        : "r"(a[0]), "r"(a[1]), "r"(a[2]), "r"(a[3]), "r"(b[0]), "r"(b[1]));
}
#define CP_ASYNC16(sa, ga) \
    asm volatile("cp.async.cg.shared.global [%0], [%1], 16;" :: "r"(sa), "l"(ga))
#define CP_COMMIT() asm volatile("cp.async.commit_group;")
#define CP_WAIT1() asm volatile("cp.async.wait_group 1;")
#define CP_WAIT0() asm volatile("cp.async.wait_group 0;")

// ---------------------------------------------------------------------------
// Weight conversion: w_eff = w * WSCALE -> fp16
// ---------------------------------------------------------------------------
__global__ void wconv_kernel(const float* __restrict__ w,
                             __half* __restrict__ wh) {
    size_t i = (size_t)blockIdx.x * blockDim.x + threadIdx.x;
    float4 v = ((const float4*)w)[i];
    union { uint2 u; __half h[4]; } ph;
    ph.h[0] = __float2half_rn(v.x * WSCALE);
    ph.h[1] = __float2half_rn(v.y * WSCALE);
    ph.h[2] = __float2half_rn(v.z * WSCALE);
    ph.h[3] = __float2half_rn(v.w * WSCALE);
    ((uint2*)wh)[i] = ph.u;
}

// ---------------------------------------------------------------------------
// Pixel norm -> fp16
// ---------------------------------------------------------------------------
__global__ void pixelnorm_kernel(const float* __restrict__ z,
                                 __half* __restrict__ a) {
    const int row = blockIdx.x;
    const int tid = threadIdx.x;
    float4 v = ((const float4*)(z + (size_t)row * HID))[tid];
    float s = v.x * v.x + v.y * v.y + v.z * v.z + v.w * v.w;
#pragma unroll
    for (int o = 16; o > 0; o >>= 1) s += __shfl_xor_sync(0xffffffffu, s, o);
    __shared__ float ws[4];
    if ((tid & 31) == 0) ws[tid >> 5] = s;
    __syncthreads();
    float tot = ws[0] + ws[1] + ws[2] + ws[3];
    float r = rsqrtf(tot * (1.0f / HID) + EPSV);
    union { uint2 u; __half h[4]; } ph;
    ph.h[0] = __float2half_rn(v.x * r);
    ph.h[1] = __float2half_rn(v.y * r);
    ph.h[2] = __float2half_rn(v.z * r);
    ph.h[3] = __float2half_rn(v.w * r);
    ((uint2*)a)[((size_t)row * HID) / 4 + tid] = ph.u;
}

// ---------------------------------------------------------------------------
// Single-term fp16 HMMA GEMM layer.  C[m,n] = sum_k a[m,k] * w_eff[n,k]
// Tile BM=128 x BN=128, BK=32, 128 threads (2m x 2n warps), warp tile 64x64
// (128 LDSM-bytes/MMA), 3-stage cp.async ring with the R7-validated
// single-barrier ordering (wait -> sync -> issue(s+2) -> compute(s)),
// 2 CTAs/SM.  SMEM rows: 32 half = 64 B data, stride 80 B (conflict-free).
// ---------------------------------------------------------------------------
#define RSTRIDE 80
#define PLANE_BYTES (128 * RSTRIDE)      /* 10240 */
#define STAGE_BYTES (2 * PLANE_BYTES)    /* 20480 */
#define NSTAGE 3
#define SMEM_TOTAL (NSTAGE * STAGE_BYTES) /* 61440 */
#define OFF_A 0
#define OFF_B PLANE_BYTES
#define KSTAGES 16

__device__ __forceinline__ void load_stage(uint32_t sp,
                                           const __half* __restrict__ A,
                                           const __half* __restrict__ W,
                                           int bm, int bn, int kb, int tid) {
    // A plane: 128 rows x 4 units = 512 cp.async (4/thread)
#pragma unroll
    for (int h = 0; h < 4; h++) {
        int u = tid + h * 128;
        int row = u >> 2, un = u & 3;
        CP_ASYNC16(sp + OFF_A + row * RSTRIDE + un * 16,
                   A + (size_t)(bm + row) * HID + kb + un * 8);
    }
    // B plane: 128 rows x 4 units = 512 cp.async (4/thread)
#pragma unroll
    for (int h = 0; h < 4; h++) {
        int u = tid + h * 128;
        int row = u >> 2, un = u & 3;
        CP_ASYNC16(sp + OFF_B + row * RSTRIDE + un * 16,
                   W + (size_t)(bn + row) * HID + kb + un * 8);
    }
}

template <bool LAST>
__global__ __launch_bounds__(128, 2) void gemm_layer(
    const __half* __restrict__ A, const __half* __restrict__ W,
    const float* __restrict__ bias, __half* __restrict__ O,
    float* __restrict__ OutF) {
    extern __shared__ char smem[];
    const uint32_t sb = smem_u32(smem);
    const int tid = threadIdx.x;
    const int wid = tid >> 5;
    const int lid = tid & 31;
    const int wm = wid >> 1;            // 0..1 -> 64 rows each
    const int wn = wid & 1;             // 0..1 -> 64 cols each
    const int bm = blockIdx.y * 128;
    const int bn = blockIdx.x * 128;

    const int lt = lid >> 3;            // ldmatrix tile index 0..3
    const int li = lid & 7;

    const int am_row = wm * 64 + (lt & 1) * 8 + li;
    const int bn_row0 = wn * 64 + (lt >> 1) * 8 + li;
    uint32_t aoff[4], boff[4];
#pragma unroll
    for (int mf = 0; mf < 4; mf++)
        aoff[mf] = OFF_A + (am_row + mf * 16) * RSTRIDE + (lt >> 1) * 16;
#pragma unroll
    for (int p = 0; p < 4; p++)
        boff[p] = OFF_B + (bn_row0 + p * 16) * RSTRIDE + (lt & 1) * 16;

    float acc[4][8][4];
#pragma unroll
    for (int a = 0; a < 4; a++)
#pragma unroll
        for (int b = 0; b < 8; b++)
#pragma unroll
            for (int c = 0; c < 4; c++) acc[a][b][c] = 0.0f;

    // prologue: stages 0,1 into ring buffers 0,1
#pragma unroll
    for (int s = 0; s < 2; s++) {
        load_stage(sb + s * STAGE_BYTES, A, W, bm, bn, s * 32, tid);
        CP_COMMIT();
    }

    uint32_t sc = sb;                        // compute buffer (stage s)
    uint32_t sp = sb + 2 * STAGE_BYTES;      // prefetch buffer (stage s+2)

    for (int s = 0; s < KSTAGES; s++) {
        // R7-validated single-barrier ordering:
        // own-wait (group s done) -> barrier (publishes all threads' stage-s
        // data AND orders compute(s-1) before buffer (s+2)%3==(s-1)%3 reuse)
        // -> issue loads(s+2) -> compute(s).
        if (s < KSTAGES - 1) CP_WAIT1();
        else CP_WAIT0();
        __syncthreads();
        if (s + 2 < KSTAGES) {
            load_stage(sp, A, W, bm, bn, (s + 2) * 32, tid);
            CP_COMMIT();
        }

#pragma unroll
        for (int kk = 0; kk < 2; kk++) {
            uint32_t ah[4][4];
#pragma unroll
            for (int mf = 0; mf < 4; mf++)
                ldm_x4(sc + aoff[mf] + kk * 32, ah[mf]);
            uint32_t bh[8][2];
#pragma unroll
            for (int p = 0; p < 4; p++) {
                uint32_t r[4];
                ldm_x4(sc + boff[p] + kk * 32, r);
                bh[2 * p][0] = r[0]; bh[2 * p][1] = r[1];
                bh[2 * p + 1][0] = r[2]; bh[2 * p + 1][1] = r[3];
            }
#pragma unroll
            for (int mf = 0; mf < 4; mf++)
#pragma unroll
                for (int nf = 0; nf < 8; nf++)
                    mma16816(acc[mf][nf], ah[mf], bh[nf]);
        }
        // rotate ring pointers
        sc += STAGE_BYTES;
        if (sc == sb + NSTAGE * STAGE_BYTES) sc = sb;
        sp += STAGE_BYTES;
        if (sp == sb + NSTAGE * STAGE_BYTES) sp = sb;
    }

    // Epilogue: m16n8 c mapping: reg e -> row=(l/4)+(e>=2?8:0), col=(l%4)*2+(e&1)
    float bj[8][2];
#pragma unroll
    for (int nf = 0; nf < 8; nf++) {
        int col = bn + wn * 64 + nf * 8 + (lid & 3) * 2;
        bj[nf][0] = bias[col] * BSCALE;
        bj[nf][1] = bias[col + 1] * BSCALE;
    }

#pragma unroll
    for (int mf = 0; mf < 4; mf++) {
#pragma unroll
        for (int half_ : {0, 1}) {
            int row = bm + wm * 64 + mf * 16 + (lid >> 2) + half_ * 8;
#pragma unroll
            for (int nf = 0; nf < 8; nf++) {
                int col = bn + wn * 64 + nf * 8 + (lid & 3) * 2;
                float x0 = acc[mf][nf][half_ * 2 + 0] + bj[nf][0];
                float x1 = acc[mf][nf][half_ * 2 + 1] + bj[nf][1];
                x0 = (x0 > 0.0f ? x0 : SLOPE * x0) * GAIN;
                x1 = (x1 > 0.0f ? x1 : SLOPE * x1) * GAIN;
                if (!LAST) {
                    size_t off = (size_t)row * HID + col;
                    *(__half2*)(O + off) =
                        __halves2half2(__float2half_rn(x0), __float2half_rn(x1));
                } else {
                    float2 p = make_float2(x0, x1);
#pragma unroll
                    for (int r = 0; r < NOUT; r++) {
                        size_t off = ((size_t)row * NOUT + r) * HID + col;
                        *(float2*)(OutF + off) = p;
                    }
                }
            }
        }
    }
}

// ---------------------------------------------------------------------------
extern "C" void kernel_launch(void* const* d_in, const int* in_sizes, int n_in,
                              void* d_out, int out_size) {
    const float* z = (const float*)d_in[0];
    const float* weight = (const float*)d_in[1];
    const float* bias = (const float*)d_in[2];
    float* out = (float*)d_out;

    __half *a, *w;
    cudaGetSymbolAddress((void**)&a, g_A);
    cudaGetSymbolAddress((void**)&w, g_W);

    cudaFuncSetAttribute(gemm_layer<false>,
                         cudaFuncAttributeMaxDynamicSharedMemorySize, SMEM_TOTAL);
    cudaFuncSetAttribute(gemm_layer<true>,
                         cudaFuncAttributeMaxDynamicSharedMemorySize, SMEM_TOTAL);

    wconv_kernel<<<2048, 256>>>(weight, w);
    pixelnorm_kernel<<<BATCH, 128>>>(z, a);

    const size_t ABUF = (size_t)BATCH * HID;
    const size_t WBUF = (size_t)HID * HID;
    dim3 grid(HID / 128, BATCH / 128);  // (4, 128) = 512 CTAs
    for (int l = 0; l < NLAYERS; l++) {
        const __half* Ain = a + (l & 1) * ABUF;
        __half* Aout = a + ((l + 1) & 1) * ABUF;
        const __half* Wl = w + (size_t)l * WBUF;
        const float* bl = bias + (size_t)l * HID;
        if (l == NLAYERS - 1)
            gemm_layer<true><<<grid, 128, SMEM_TOTAL>>>(Ain, Wl, bl, nullptr,
                                                        out);
        else
            gemm_layer<false><<<grid, 128, SMEM_TOTAL>>>(Ain, Wl, bl, Aout,
                                                         nullptr);
    }
}